// round 2
// baseline (speedup 1.0000x reference)
#include <cuda_runtime.h>
#include <cstdint>
#include <cstddef>

// Problem constants
#define NCTA 128
#define TPB  256
constexpr int Bsz = 512;
constexpr int Tsz = 256;
constexpr int Hsz = 256;
constexpr int Psz = 14;

// Scratch (device globals — allowed; no dynamic allocation anywhere)
__device__ float g_h1[(size_t)Tsz * Bsz * Hsz];   // layer-0 outputs (history), 128 MB
__device__ float g_h2[2][Bsz * Hsz];              // layer-1 h double buffer
__device__ unsigned g_bar_count = 0;
__device__ volatile unsigned g_bar_gen = 0;

__device__ __forceinline__ float sigf(float x) { return 1.0f / (1.0f + __expf(-x)); }

// Grid-wide barrier. All 128 CTAs are co-resident (grid <= #SMs, occupancy 1).
__device__ __forceinline__ void grid_barrier(unsigned* sgen) {
    __threadfence();            // each thread publishes its global stores
    __syncthreads();            // all threads of CTA have fenced
    if (threadIdx.x == 0) {
        unsigned target = *sgen + 1;
        if (atomicAdd(&g_bar_count, 1u) == NCTA - 1) {
            g_bar_count = 0;
            __threadfence();
            g_bar_gen = target;
        } else {
            while (g_bar_gen < target) { __nanosleep(64); }
        }
        __threadfence();        // acquire
        *sgen = target;
    }
    __syncthreads();
}

__global__ void __launch_bounds__(TPB, 1)
lstm_kernel(const float* __restrict__ x,
            const float* __restrict__ w_ih0, const float* __restrict__ w_hh0,
            const float* __restrict__ b_ih0, const float* __restrict__ b_hh0,
            const float* __restrict__ w_ih1, const float* __restrict__ w_hh1,
            const float* __restrict__ b_ih1, const float* __restrict__ b_hh1,
            const float* __restrict__ w_lin, const float* __restrict__ b_lin,
            float* __restrict__ out)
{
    extern __shared__ float smem[];
    __shared__ unsigned sgen;
    const int tid  = threadIdx.x;
    const int cta  = blockIdx.x;
    const int lane = tid & 31;
    const int warp = tid >> 5;

    if (tid == 0) sgen = g_bar_gen;   // safe: gen can't advance before all CTAs read it
    __syncthreads();

    // ================= Layer 0 =================
    // Partition: 8 col-chunks (32 h-cols each) x 16 batch-chunks (32 rows each).
    {
        const int cblk = cta & 7;
        const int rblk = cta >> 3;
        float* Wsh = smem;              // [128 rows][stride 260]  row rr = gate*32 + j
        float* hsh = smem + 128 * 260;  // [32][256]

        for (int idx = tid; idx < 128 * 64; idx += TPB) {
            int rr = idx >> 6, k4 = idx & 63;
            int g = rr >> 5, j = rr & 31;
            int n = g * Hsz + cblk * 32 + j;
            float4 v = *(const float4*)(w_hh0 + (size_t)n * Hsz + k4 * 4);
            *(float4*)(Wsh + rr * 260 + k4 * 4) = v;
        }
        float wih_r[4], bias_r[4];
        #pragma unroll
        for (int g = 0; g < 4; g++) {
            int n = g * Hsz + cblk * 32 + lane;
            wih_r[g]  = w_ih0[n];
            bias_r[g] = b_ih0[n] + b_hh0[n];
        }
        const int bbase = rblk * 32 + warp * 4;
        float creg[4] = {0.f, 0.f, 0.f, 0.f};
        __syncthreads();

        for (int t = 0; t < Tsz; t++) {
            if (t > 0) {   // stage h_prev tile [32 x 256] via L2 (cross-CTA data)
                const float* hp = g_h1 + ((size_t)(t - 1) * Bsz + rblk * 32) * Hsz;
                for (int idx = tid; idx < 32 * 64; idx += TPB) {
                    int r = idx >> 6, k4 = idx & 63;
                    float4 v = __ldcg((const float4*)(hp + (size_t)r * Hsz + k4 * 4));
                    *(float4*)(hsh + r * 256 + k4 * 4) = v;
                }
            }
            __syncthreads();

            float acc[4][4];
            #pragma unroll
            for (int bb = 0; bb < 4; bb++) {
                float xv = __ldg(x + (size_t)(bbase + bb) * Tsz + t);
                #pragma unroll
                for (int g = 0; g < 4; g++) acc[bb][g] = fmaf(xv, wih_r[g], bias_r[g]);
            }
            if (t > 0) {
                const float* wp = Wsh + lane * 260;
                const float* hq = hsh + warp * 4 * 256;
                #pragma unroll 2
                for (int k = 0; k < 256; k += 4) {
                    float4 h4[4], w4[4];
                    #pragma unroll
                    for (int bb = 0; bb < 4; bb++) h4[bb] = *(const float4*)(hq + bb * 256 + k);
                    #pragma unroll
                    for (int g = 0; g < 4; g++)  w4[g] = *(const float4*)(wp + g * (32 * 260) + k);
                    #pragma unroll
                    for (int bb = 0; bb < 4; bb++) {
                        #pragma unroll
                        for (int g = 0; g < 4; g++) {
                            acc[bb][g] = fmaf(h4[bb].x, w4[g].x, acc[bb][g]);
                            acc[bb][g] = fmaf(h4[bb].y, w4[g].y, acc[bb][g]);
                            acc[bb][g] = fmaf(h4[bb].z, w4[g].z, acc[bb][g]);
                            acc[bb][g] = fmaf(h4[bb].w, w4[g].w, acc[bb][g]);
                        }
                    }
                }
            }
            float* hout = g_h1 + (size_t)t * Bsz * Hsz + (size_t)cblk * 32 + lane;
            #pragma unroll
            for (int bb = 0; bb < 4; bb++) {
                float iv = sigf(acc[bb][0]);
                float fv = sigf(acc[bb][1]);
                float gv = tanhf(acc[bb][2]);
                float ov = sigf(acc[bb][3]);
                float c  = fmaf(fv, creg[bb], iv * gv);
                creg[bb] = c;
                hout[(size_t)(bbase + bb) * Hsz] = ov * tanhf(c);
            }
            grid_barrier(&sgen);
        }
    }

    // ================= Layer 1 =================
    // Partition: 16 col-chunks (16 h-cols) x 8 batch-chunks (64 rows).
    // K = 512: cols [0,256) = w_ih1 (input h1[t]), cols [256,512) = w_hh1 (h2[t-1]).
    {
        const int cblk = cta & 15;
        const int rblk = cta >> 4;
        float* Wsh = smem;              // [64 rows][stride 516]  row rr = gate*16 + j
        float* hsh = smem + 64 * 516;   // [64][256]

        for (int idx = tid; idx < 64 * 128; idx += TPB) {
            int rr = idx >> 7, k4 = idx & 127;
            int g = rr >> 4, j = rr & 15;
            int n = g * Hsz + cblk * 16 + j;
            const float* src = (k4 < 64) ? (w_ih1 + (size_t)n * Hsz + k4 * 4)
                                         : (w_hh1 + (size_t)n * Hsz + (k4 - 64) * 4);
            *(float4*)(Wsh + rr * 516 + k4 * 4) = *(const float4*)src;
        }
        const int jcol = lane & 15;
        const int half = lane >> 4;
        float bias_r[4];
        #pragma unroll
        for (int g = 0; g < 4; g++) {
            int n = g * Hsz + cblk * 16 + jcol;
            bias_r[g] = b_ih1[n] + b_hh1[n];
        }
        const int bbase = rblk * 64 + warp * 8 + half * 4;
        float creg[4] = {0.f, 0.f, 0.f, 0.f};
        __syncthreads();

        for (int t = 0; t < Tsz; t++) {
            // ---- panel 0: h1[t] ----
            {
                const float* hp = g_h1 + ((size_t)t * Bsz + rblk * 64) * Hsz;
                for (int idx = tid; idx < 64 * 64; idx += TPB) {
                    int r = idx >> 6, k4 = idx & 63;
                    float4 v = __ldcg((const float4*)(hp + (size_t)r * Hsz + k4 * 4));
                    *(float4*)(hsh + r * 256 + k4 * 4) = v;
                }
            }
            __syncthreads();

            float acc[4][4];
            #pragma unroll
            for (int bb = 0; bb < 4; bb++)
                #pragma unroll
                for (int g = 0; g < 4; g++) acc[bb][g] = bias_r[g];

            {
                const float* wp = Wsh + jcol * 516;
                const float* hq = hsh + (warp * 8 + half * 4) * 256;
                #pragma unroll 2
                for (int k = 0; k < 256; k += 4) {
                    float4 h4[4], w4[4];
                    #pragma unroll
                    for (int bb = 0; bb < 4; bb++) h4[bb] = *(const float4*)(hq + bb * 256 + k);
                    #pragma unroll
                    for (int g = 0; g < 4; g++)  w4[g] = *(const float4*)(wp + g * (16 * 516) + k);
                    #pragma unroll
                    for (int bb = 0; bb < 4; bb++) {
                        #pragma unroll
                        for (int g = 0; g < 4; g++) {
                            acc[bb][g] = fmaf(h4[bb].x, w4[g].x, acc[bb][g]);
                            acc[bb][g] = fmaf(h4[bb].y, w4[g].y, acc[bb][g]);
                            acc[bb][g] = fmaf(h4[bb].z, w4[g].z, acc[bb][g]);
                            acc[bb][g] = fmaf(h4[bb].w, w4[g].w, acc[bb][g]);
                        }
                    }
                }
            }
            __syncthreads();   // done reading panel-0 hsh

            // ---- panel 1: h2[t-1] ----
            if (t > 0) {
                const float* hp = g_h2[t & 1] + (size_t)rblk * 64 * Hsz;
                for (int idx = tid; idx < 64 * 64; idx += TPB) {
                    int r = idx >> 6, k4 = idx & 63;
                    float4 v = __ldcg((const float4*)(hp + (size_t)r * Hsz + k4 * 4));
                    *(float4*)(hsh + r * 256 + k4 * 4) = v;
                }
            }
            __syncthreads();
            if (t > 0) {
                const float* wp = Wsh + jcol * 516 + 256;
                const float* hq = hsh + (warp * 8 + half * 4) * 256;
                #pragma unroll 2
                for (int k = 0; k < 256; k += 4) {
                    float4 h4[4], w4[4];
                    #pragma unroll
                    for (int bb = 0; bb < 4; bb++) h4[bb] = *(const float4*)(hq + bb * 256 + k);
                    #pragma unroll
                    for (int g = 0; g < 4; g++)  w4[g] = *(const float4*)(wp + g * (16 * 516) + k);
                    #pragma unroll
                    for (int bb = 0; bb < 4; bb++) {
                        #pragma unroll
                        for (int g = 0; g < 4; g++) {
                            acc[bb][g] = fmaf(h4[bb].x, w4[g].x, acc[bb][g]);
                            acc[bb][g] = fmaf(h4[bb].y, w4[g].y, acc[bb][g]);
                            acc[bb][g] = fmaf(h4[bb].z, w4[g].z, acc[bb][g]);
                            acc[bb][g] = fmaf(h4[bb].w, w4[g].w, acc[bb][g]);
                        }
                    }
                }
            }

            float* hob = g_h2[(t + 1) & 1] + (size_t)cblk * 16 + jcol;
            #pragma unroll
            for (int bb = 0; bb < 4; bb++) {
                float iv = sigf(acc[bb][0]);
                float fv = sigf(acc[bb][1]);
                float gv = tanhf(acc[bb][2]);
                float c  = fmaf(fv, creg[bb], iv * gv);
                creg[bb] = c;
                float ov = sigf(acc[bb][3]);
                hob[(size_t)(bbase + bb) * Hsz] = ov * tanhf(c);
            }
            grid_barrier(&sgen);
        }
    }

    // ================= Final linear =================
    // h2 at t = T-1 lives in g_h2[Tsz & 1] == g_h2[0]
    if (cta < 16) {
        const float* h2 = g_h2[Tsz & 1];
        for (int idx = tid; idx < 32 * Psz; idx += TPB) {
            int b = cta * 32 + idx / Psz;
            int p = idx % Psz;
            const float* hr = h2 + (size_t)b * Hsz;
            const float* wr = w_lin + (size_t)p * Hsz;
            float s = b_lin[p];
            for (int k = 0; k < Hsz; k += 4) {
                float4 hv = __ldcg((const float4*)(hr + k));
                float4 wv = *(const float4*)(wr + k);
                s += hv.x * wv.x + hv.y * wv.y + hv.z * wv.z + hv.w * wv.w;
            }
            out[(size_t)b * Psz + p] = s;
        }
    }
}

extern "C" void kernel_launch(void* const* d_in, const int* in_sizes, int n_in,
                              void* d_out, int out_size) {
    // Dynamic smem: max(layer0: 128*260*4 + 32*256*4, layer1: 64*516*4 + 64*256*4)
    const int smem_bytes = 64 * 516 * 4 + 64 * 256 * 4;   // 197,632 B
    cudaFuncSetAttribute(lstm_kernel, cudaFuncAttributeMaxDynamicSharedMemorySize, smem_bytes);

    const float* xx    = (const float*)d_in[0];
    const float* wih0  = (const float*)d_in[1];
    const float* whh0  = (const float*)d_in[2];
    const float* bih0  = (const float*)d_in[3];
    const float* bhh0  = (const float*)d_in[4];
    const float* wih1  = (const float*)d_in[5];
    const float* whh1  = (const float*)d_in[6];
    const float* bih1  = (const float*)d_in[7];
    const float* bhh1  = (const float*)d_in[8];
    const float* wlin  = (const float*)d_in[9];
    const float* blin  = (const float*)d_in[10];

    lstm_kernel<<<NCTA, TPB, smem_bytes>>>(xx, wih0, whh0, bih0, bhh0,
                                           wih1, whh1, bih1, bhh1,
                                           wlin, blin, (float*)d_out);
}

// round 6
// speedup vs baseline: 1.4600x; 1.4600x over previous
#include <cuda_runtime.h>
#include <cuda_bf16.h>
#include <cstdint>
#include <cstddef>

#define NCTA 128
#define TPB  128
constexpr int Bsz = 512;
constexpr int Tsz = 256;
constexpr int Hsz = 256;
constexpr int Psz = 14;

// ---------------- device scratch ----------------
__device__ __nv_bfloat16 g_h1_hi[(size_t)Tsz * Bsz * Hsz];   // 64 MB
__device__ __nv_bfloat16 g_h1_lo[(size_t)Tsz * Bsz * Hsz];   // 64 MB
__device__ __nv_bfloat16 g_h2_hi[2][Bsz * Hsz];
__device__ __nv_bfloat16 g_h2_lo[2][Bsz * Hsz];
__device__ unsigned g_bar_count = 0;
__device__ volatile unsigned g_bar_gen = 0;

__device__ __forceinline__ float sigf(float x) { return 1.0f / (1.0f + __expf(-x)); }
__device__ __forceinline__ float tanh_f(float x) {
    x = fmaxf(fminf(x, 15.f), -15.f);
    float e = __expf(-2.f * x);
    return __fdividef(1.f - e, 1.f + e);
}

// grid barrier (validated in R2)
__device__ __forceinline__ void grid_barrier(unsigned* sgen) {
    __threadfence();
    __syncthreads();
    if (threadIdx.x == 0) {
        unsigned target = *sgen + 1;
        if (atomicAdd(&g_bar_count, 1u) == NCTA - 1) {
            g_bar_count = 0;
            __threadfence();
            g_bar_gen = target;
        } else {
            while (g_bar_gen < target) { __nanosleep(64); }
        }
        __threadfence();
        *sgen = target;
    }
    __syncthreads();
}

// ---------------- smem layout (bytes) ----------------
// A: [64 rows][264 bf16]  (stride 528B -> bank shift 4/row, conflict-free frags)
// W: [64 rows][520 bf16]  (stride 1040B -> same property; k up to 512)
// D: [64][65 f32]         (stride 65 words -> bank shift 1/row)
#define ASTR 528
#define WSTR 1040
#define DSTR 65
#define OFF_AHI 0u
#define OFF_ALO 33792u
#define OFF_WHI 67584u
#define OFF_WLO 134144u
#define OFF_D   200704u
#define OFF_MISC 217344u
#define SMEM_DYN (217344 + 512)

#define MMA4(d, a, b0_, b1_) \
  asm volatile("mma.sync.aligned.m16n8k16.row.col.f32.bf16.bf16.f32 " \
   "{%0,%1,%2,%3}, {%4,%5,%6,%7}, {%8,%9}, {%0,%1,%2,%3};\n" \
   : "+f"((d)[0]), "+f"((d)[1]), "+f"((d)[2]), "+f"((d)[3]) \
   : "r"((a)[0]), "r"((a)[1]), "r"((a)[2]), "r"((a)[3]), "r"(b0_), "r"(b1_))

union BV8 { __nv_bfloat16 b[8]; uint4 v; };

__global__ void __launch_bounds__(TPB, 1)
lstm_hmma_kernel(const float* __restrict__ x,
                 const float* __restrict__ w_ih0, const float* __restrict__ w_hh0,
                 const float* __restrict__ b_ih0, const float* __restrict__ b_hh0,
                 const float* __restrict__ w_ih1, const float* __restrict__ w_hh1,
                 const float* __restrict__ b_ih1, const float* __restrict__ b_hh1,
                 const float* __restrict__ w_lin, const float* __restrict__ b_lin,
                 float* __restrict__ out)
{
    extern __shared__ __align__(16) unsigned char sb[];
    __shared__ unsigned sgen;

    const int tid  = threadIdx.x;
    const int cta  = blockIdx.x;
    const int lane = tid & 31;
    const int warp = tid >> 5;
    const int grp  = lane >> 2;      // 0..7
    const int tig  = lane & 3;       // 0..3

    const int mtile = cta >> 4;      // 0..7  : batch rows mtile*64..+64
    const int ctile = cta & 15;      // 0..15 : hidden units ctile*16..+16
    const int hc0   = ctile * 16;

    float* sD    = (float*)(sb + OFF_D);
    float* sBias = (float*)(sb + OFF_MISC);        // [64]
    float* sWih  = sBias + 64;                     // [64]

    if (tid == 0) sgen = g_bar_gen;
    __syncthreads();

    // epilogue mapping: thread -> (row er, 8 units starting ej)
    const int er = tid & 63;
    const int ej = (tid >> 6) * 8;
    const int gbrow = mtile * 64 + er;

    // fragment base row for this warp's m-tile
    const int ar0 = warp * 16 + grp;

    // ================= Layer 0 =================
    {
        // stage W_hh0 (cols = gate*16+j  <->  n = gate*256 + hc0 + j) as hi/lo
        for (int idx = tid; idx < 2048; idx += TPB) {
            int rr = idx >> 5, k0 = (idx & 31) * 8;
            int n = (rr >> 4) * Hsz + hc0 + (rr & 15);
            const float* s = w_hh0 + (size_t)n * Hsz + k0;
            float4 f0 = *(const float4*)s, f1 = *(const float4*)(s + 4);
            float fv[8] = {f0.x, f0.y, f0.z, f0.w, f1.x, f1.y, f1.z, f1.w};
            BV8 uh, ul;
            #pragma unroll
            for (int i = 0; i < 8; i++) {
                uh.b[i] = __float2bfloat16(fv[i]);
                ul.b[i] = __float2bfloat16(fv[i] - __bfloat162float(uh.b[i]));
            }
            *(uint4*)(sb + OFF_WHI + (size_t)rr * WSTR + k0 * 2) = uh.v;
            *(uint4*)(sb + OFF_WLO + (size_t)rr * WSTR + k0 * 2) = ul.v;
        }
        for (int idx = tid; idx < 64; idx += TPB) {
            int n = (idx >> 4) * Hsz + hc0 + (idx & 15);
            sBias[idx] = b_ih0[n] + b_hh0[n];
            sWih[idx]  = w_ih0[n];
        }
        __syncthreads();

        float cst[8];
        #pragma unroll
        for (int i = 0; i < 8; i++) cst[i] = 0.f;

        for (int t = 0; t < Tsz; t++) {
            if (t > 0) {
                // stage A = h_prev[64 x 256] hi/lo
                const __nv_bfloat16* shi = g_h1_hi + ((size_t)(t - 1) * Bsz + mtile * 64) * Hsz;
                const __nv_bfloat16* slo = g_h1_lo + ((size_t)(t - 1) * Bsz + mtile * 64) * Hsz;
                for (int idx = tid; idx < 2048; idx += TPB) {
                    int r = idx >> 5, c8 = (idx & 31) * 8;
                    *(uint4*)(sb + OFF_AHI + (size_t)r * ASTR + c8 * 2) =
                        __ldcg((const uint4*)(shi + (size_t)r * Hsz + c8));
                    *(uint4*)(sb + OFF_ALO + (size_t)r * ASTR + c8 * 2) =
                        __ldcg((const uint4*)(slo + (size_t)r * Hsz + c8));
                }
                __syncthreads();

                float acc[8][4];
                #pragma unroll
                for (int nt = 0; nt < 8; nt++)
                    #pragma unroll
                    for (int i = 0; i < 4; i++) acc[nt][i] = 0.f;

                #pragma unroll 4
                for (int ks = 0; ks < 16; ks++) {
                    int kb = ks * 16 + 2 * tig;
                    uint32_t ah[4], al[4];
                    ah[0] = *(const uint32_t*)(sb + OFF_AHI + (size_t)ar0 * ASTR + kb * 2);
                    ah[1] = *(const uint32_t*)(sb + OFF_AHI + (size_t)(ar0 + 8) * ASTR + kb * 2);
                    ah[2] = *(const uint32_t*)(sb + OFF_AHI + (size_t)ar0 * ASTR + (kb + 8) * 2);
                    ah[3] = *(const uint32_t*)(sb + OFF_AHI + (size_t)(ar0 + 8) * ASTR + (kb + 8) * 2);
                    al[0] = *(const uint32_t*)(sb + OFF_ALO + (size_t)ar0 * ASTR + kb * 2);
                    al[1] = *(const uint32_t*)(sb + OFF_ALO + (size_t)(ar0 + 8) * ASTR + kb * 2);
                    al[2] = *(const uint32_t*)(sb + OFF_ALO + (size_t)ar0 * ASTR + (kb + 8) * 2);
                    al[3] = *(const uint32_t*)(sb + OFF_ALO + (size_t)(ar0 + 8) * ASTR + (kb + 8) * 2);
                    #pragma unroll
                    for (int nt = 0; nt < 8; nt++) {
                        int bn = nt * 8 + grp;
                        uint32_t bh0 = *(const uint32_t*)(sb + OFF_WHI + (size_t)bn * WSTR + kb * 2);
                        uint32_t bh1 = *(const uint32_t*)(sb + OFF_WHI + (size_t)bn * WSTR + (kb + 8) * 2);
                        uint32_t bl0 = *(const uint32_t*)(sb + OFF_WLO + (size_t)bn * WSTR + kb * 2);
                        uint32_t bl1 = *(const uint32_t*)(sb + OFF_WLO + (size_t)bn * WSTR + (kb + 8) * 2);
                        MMA4(acc[nt], ah, bh0, bh1);
                        MMA4(acc[nt], al, bh0, bh1);
                        MMA4(acc[nt], ah, bl0, bl1);
                    }
                }
                // write accumulators to D
                #pragma unroll
                for (int nt = 0; nt < 8; nt++) {
                    int c0 = nt * 8 + 2 * tig;
                    sD[(size_t)ar0 * DSTR + c0]           = acc[nt][0];
                    sD[(size_t)ar0 * DSTR + c0 + 1]       = acc[nt][1];
                    sD[(size_t)(ar0 + 8) * DSTR + c0]     = acc[nt][2];
                    sD[(size_t)(ar0 + 8) * DSTR + c0 + 1] = acc[nt][3];
                }
            }
            __syncthreads();

            // epilogue
            float xv = __ldg(x + (size_t)gbrow * Tsz + t);
            BV8 hh, hl;
            #pragma unroll
            for (int q = 0; q < 8; q++) {
                int j = ej + q;
                float pi = sBias[j]      + xv * sWih[j];
                float pf = sBias[16 + j] + xv * sWih[16 + j];
                float pg = sBias[32 + j] + xv * sWih[32 + j];
                float po = sBias[48 + j] + xv * sWih[48 + j];
                if (t > 0) {
                    pi += sD[(size_t)er * DSTR + j];
                    pf += sD[(size_t)er * DSTR + 16 + j];
                    pg += sD[(size_t)er * DSTR + 32 + j];
                    po += sD[(size_t)er * DSTR + 48 + j];
                }
                float iv = sigf(pi), fv = sigf(pf), gv = tanh_f(pg), ov = sigf(po);
                float c  = fmaf(fv, cst[q], iv * gv);
                cst[q] = c;
                float h  = ov * tanh_f(c);
                hh.b[q] = __float2bfloat16(h);
                hl.b[q] = __float2bfloat16(h - __bfloat162float(hh.b[q]));
            }
            size_t ho = ((size_t)t * Bsz + gbrow) * Hsz + hc0 + ej;
            *(uint4*)(g_h1_hi + ho) = hh.v;
            *(uint4*)(g_h1_lo + ho) = hl.v;
            grid_barrier(&sgen);
        }
    }

    // ================= Layer 1 =================
    {
        // stage [w_ih1 | w_hh1] as 64 x 512 hi/lo
        for (int idx = tid; idx < 4096; idx += TPB) {
            int rr = idx >> 6, k0 = (idx & 63) * 8;
            int n = (rr >> 4) * Hsz + hc0 + (rr & 15);
            const float* s = (k0 < 256) ? (w_ih1 + (size_t)n * Hsz + k0)
                                        : (w_hh1 + (size_t)n * Hsz + (k0 - 256));
            float4 f0 = *(const float4*)s, f1 = *(const float4*)(s + 4);
            float fv[8] = {f0.x, f0.y, f0.z, f0.w, f1.x, f1.y, f1.z, f1.w};
            BV8 uh, ul;
            #pragma unroll
            for (int i = 0; i < 8; i++) {
                uh.b[i] = __float2bfloat16(fv[i]);
                ul.b[i] = __float2bfloat16(fv[i] - __bfloat162float(uh.b[i]));
            }
            *(uint4*)(sb + OFF_WHI + (size_t)rr * WSTR + k0 * 2) = uh.v;
            *(uint4*)(sb + OFF_WLO + (size_t)rr * WSTR + k0 * 2) = ul.v;
        }
        for (int idx = tid; idx < 64; idx += TPB) {
            int n = (idx >> 4) * Hsz + hc0 + (idx & 15);
            sBias[idx] = b_ih1[n] + b_hh1[n];
        }
        __syncthreads();

        float cst[8];
        #pragma unroll
        for (int i = 0; i < 8; i++) cst[i] = 0.f;

        for (int t = 0; t < Tsz; t++) {
            float acc[8][4];
            #pragma unroll
            for (int nt = 0; nt < 8; nt++)
                #pragma unroll
                for (int i = 0; i < 4; i++) acc[nt][i] = 0.f;

            const int npanels = (t > 0) ? 2 : 1;
            for (int p = 0; p < npanels; p++) {
                // stage A panel
                const __nv_bfloat16* shi;
                const __nv_bfloat16* slo;
                if (p == 0) {
                    shi = g_h1_hi + ((size_t)t * Bsz + mtile * 64) * Hsz;
                    slo = g_h1_lo + ((size_t)t * Bsz + mtile * 64) * Hsz;
                } else {
                    shi = g_h2_hi[t & 1] + (size_t)mtile * 64 * Hsz;
                    slo = g_h2_lo[t & 1] + (size_t)mtile * 64 * Hsz;
                }
                for (int idx = tid; idx < 2048; idx += TPB) {
                    int r = idx >> 5, c8 = (idx & 31) * 8;
                    *(uint4*)(sb + OFF_AHI + (size_t)r * ASTR + c8 * 2) =
                        __ldcg((const uint4*)(shi + (size_t)r * Hsz + c8));
                    *(uint4*)(sb + OFF_ALO + (size_t)r * ASTR + c8 * 2) =
                        __ldcg((const uint4*)(slo + (size_t)r * Hsz + c8));
                }
                __syncthreads();

                const int kw0 = p * 256;   // W column offset for this panel
                #pragma unroll 4
                for (int ks = 0; ks < 16; ks++) {
                    int ka = ks * 16 + 2 * tig;
                    int kb = kw0 + ka;
                    uint32_t ah[4], al[4];
                    ah[0] = *(const uint32_t*)(sb + OFF_AHI + (size_t)ar0 * ASTR + ka * 2);
                    ah[1] = *(const uint32_t*)(sb + OFF_AHI + (size_t)(ar0 + 8) * ASTR + ka * 2);
                    ah[2] = *(const uint32_t*)(sb + OFF_AHI + (size_t)ar0 * ASTR + (ka + 8) * 2);
                    ah[3] = *(const uint32_t*)(sb + OFF_AHI + (size_t)(ar0 + 8) * ASTR + (ka + 8) * 2);
                    al[0] = *(const uint32_t*)(sb + OFF_ALO + (size_t)ar0 * ASTR + ka * 2);
                    al[1] = *(const uint32_t*)(sb + OFF_ALO + (size_t)(ar0 + 8) * ASTR + ka * 2);
                    al[2] = *(const uint32_t*)(sb + OFF_ALO + (size_t)ar0 * ASTR + (ka + 8) * 2);
                    al[3] = *(const uint32_t*)(sb + OFF_ALO + (size_t)(ar0 + 8) * ASTR + (ka + 8) * 2);
                    #pragma unroll
                    for (int nt = 0; nt < 8; nt++) {
                        int bn = nt * 8 + grp;
                        uint32_t bh0 = *(const uint32_t*)(sb + OFF_WHI + (size_t)bn * WSTR + kb * 2);
                        uint32_t bh1 = *(const uint32_t*)(sb + OFF_WHI + (size_t)bn * WSTR + (kb + 8) * 2);
                        uint32_t bl0 = *(const uint32_t*)(sb + OFF_WLO + (size_t)bn * WSTR + kb * 2);
                        uint32_t bl1 = *(const uint32_t*)(sb + OFF_WLO + (size_t)bn * WSTR + (kb + 8) * 2);
                        MMA4(acc[nt], ah, bh0, bh1);
                        MMA4(acc[nt], al, bh0, bh1);
                        MMA4(acc[nt], ah, bl0, bl1);
                    }
                }
                __syncthreads();   // done reading this A panel before restage / D write
            }

            // write accumulators to D
            #pragma unroll
            for (int nt = 0; nt < 8; nt++) {
                int c0 = nt * 8 + 2 * tig;
                sD[(size_t)ar0 * DSTR + c0]           = acc[nt][0];
                sD[(size_t)ar0 * DSTR + c0 + 1]       = acc[nt][1];
                sD[(size_t)(ar0 + 8) * DSTR + c0]     = acc[nt][2];
                sD[(size_t)(ar0 + 8) * DSTR + c0 + 1] = acc[nt][3];
            }
            __syncthreads();

            // epilogue
            BV8 hh, hl;
            #pragma unroll
            for (int q = 0; q < 8; q++) {
                int j = ej + q;
                float pi = sD[(size_t)er * DSTR + j]      + sBias[j];
                float pf = sD[(size_t)er * DSTR + 16 + j] + sBias[16 + j];
                float pg = sD[(size_t)er * DSTR + 32 + j] + sBias[32 + j];
                float po = sD[(size_t)er * DSTR + 48 + j] + sBias[48 + j];
                float iv = sigf(pi), fv = sigf(pf), gv = tanh_f(pg), ov = sigf(po);
                float c  = fmaf(fv, cst[q], iv * gv);
                cst[q] = c;
                float h  = ov * tanh_f(c);
                hh.b[q] = __float2bfloat16(h);
                hl.b[q] = __float2bfloat16(h - __bfloat162float(hh.b[q]));
            }
            size_t ho = (size_t)gbrow * Hsz + hc0 + ej;
            *(uint4*)(g_h2_hi[(t + 1) & 1] + ho) = hh.v;
            *(uint4*)(g_h2_lo[(t + 1) & 1] + ho) = hl.v;
            grid_barrier(&sgen);
        }
    }

    // ================= Final linear =================
    if (cta < 16) {
        const __nv_bfloat16* hh = g_h2_hi[Tsz & 1];   // == [0]
        const __nv_bfloat16* hl = g_h2_lo[Tsz & 1];
        for (int idx = tid; idx < 32 * Psz; idx += TPB) {
            int b = cta * 32 + idx / Psz;
            int p = idx % Psz;
            const __nv_bfloat16* hr = hh + (size_t)b * Hsz;
            const __nv_bfloat16* lr = hl + (size_t)b * Hsz;
            const float* wr = w_lin + (size_t)p * Hsz;
            float s = b_lin[p];
            for (int k = 0; k < Hsz; k++) {
                float hv = __bfloat162float(hr[k]) + __bfloat162float(lr[k]);
                s = fmaf(hv, wr[k], s);
            }
            out[(size_t)b * Psz + p] = s;
        }
    }
}

extern "C" void kernel_launch(void* const* d_in, const int* in_sizes, int n_in,
                              void* d_out, int out_size) {
    cudaFuncSetAttribute(lstm_hmma_kernel, cudaFuncAttributeMaxDynamicSharedMemorySize, SMEM_DYN);
    lstm_hmma_kernel<<<NCTA, TPB, SMEM_DYN>>>(
        (const float*)d_in[0], (const float*)d_in[1], (const float*)d_in[2],
        (const float*)d_in[3], (const float*)d_in[4], (const float*)d_in[5],
        (const float*)d_in[6], (const float*)d_in[7], (const float*)d_in[8],
        (const float*)d_in[9], (const float*)d_in[10], (float*)d_out);
}

// round 11
// speedup vs baseline: 1.8066x; 1.2374x over previous
#include <cuda_runtime.h>
#include <cuda_bf16.h>
#include <cstdint>
#include <cstddef>

#define NCTA 128
#define TPB  256
constexpr int Bsz = 512;
constexpr int Tsz = 256;
constexpr int Hsz = 256;
constexpr int Psz = 14;

// ---------------- device scratch ----------------
__device__ __nv_bfloat16 g_h1_hi[(size_t)Tsz * Bsz * Hsz];   // 64 MB
__device__ __nv_bfloat16 g_h1_lo[(size_t)Tsz * Bsz * Hsz];   // 64 MB
__device__ __nv_bfloat16 g_h2_hi[2][Bsz * Hsz];
__device__ __nv_bfloat16 g_h2_lo[2][Bsz * Hsz];
__device__ unsigned g_bar_count = 0;
__device__ volatile unsigned g_bar_gen = 0;

__device__ __forceinline__ float sigf(float x) { return 1.0f / (1.0f + __expf(-x)); }
__device__ __forceinline__ float tanh_f(float x) {
    x = fmaxf(fminf(x, 15.f), -15.f);
    float e = __expf(-2.f * x);
    return __fdividef(1.f - e, 1.f + e);
}

// Grid barrier v2: one fence per CTA (cumulativity via bar.sync), no nanosleep.
__device__ __forceinline__ void grid_barrier(unsigned* sgen) {
    __syncthreads();                    // all CTA stores happen-before tid0's fence
    if (threadIdx.x == 0) {
        __threadfence();                // release (cumulative)
        unsigned target = *sgen + 1;
        if (atomicAdd(&g_bar_count, 1u) == NCTA - 1) {
            g_bar_count = 0;
            __threadfence();
            g_bar_gen = target;
        } else {
            while (g_bar_gen < target) { }   // busy spin
        }
        __threadfence();                // acquire
        *sgen = target;
    }
    __syncthreads();
}

// ---------------- smem layout (bytes) ----------------
#define ASTR 528
#define WSTR 1040
#define DSTR 65
#define OFF_AHI 0u
#define OFF_ALO 33792u
#define OFF_WHI 67584u
#define OFF_WLO 134144u
#define OFF_D   200704u
#define OFF_MISC 217344u
#define SMEM_DYN (217344 + 512)

#define MMA4(d, a, b0_, b1_) \
  asm volatile("mma.sync.aligned.m16n8k16.row.col.f32.bf16.bf16.f32 " \
   "{%0,%1,%2,%3}, {%4,%5,%6,%7}, {%8,%9}, {%0,%1,%2,%3};\n" \
   : "+f"((d)[0]), "+f"((d)[1]), "+f"((d)[2]), "+f"((d)[3]) \
   : "r"((a)[0]), "r"((a)[1]), "r"((a)[2]), "r"((a)[3]), "r"(b0_), "r"(b1_))

union BV8 { __nv_bfloat16 b[8]; uint4 v; };
union BV4 { __nv_bfloat16 b[4]; uint2 v; };

// stage a 64x256 bf16 hi/lo panel from gmem into A buffers
__device__ __forceinline__ void stage_panel(unsigned char* sb,
                                            const __nv_bfloat16* shi,
                                            const __nv_bfloat16* slo) {
    for (int idx = threadIdx.x; idx < 2048; idx += TPB) {
        int r = idx >> 5, c8 = (idx & 31) * 8;
        *(uint4*)(sb + OFF_AHI + (size_t)r * ASTR + c8 * 2) =
            __ldcg((const uint4*)(shi + (size_t)r * Hsz + c8));
        *(uint4*)(sb + OFF_ALO + (size_t)r * ASTR + c8 * 2) =
            __ldcg((const uint4*)(slo + (size_t)r * Hsz + c8));
    }
}

__global__ void __launch_bounds__(TPB, 1)
lstm_hmma_kernel(const float* __restrict__ x,
                 const float* __restrict__ w_ih0, const float* __restrict__ w_hh0,
                 const float* __restrict__ b_ih0, const float* __restrict__ b_hh0,
                 const float* __restrict__ w_ih1, const float* __restrict__ w_hh1,
                 const float* __restrict__ b_ih1, const float* __restrict__ b_hh1,
                 const float* __restrict__ w_lin, const float* __restrict__ b_lin,
                 float* __restrict__ out)
{
    extern __shared__ __align__(16) unsigned char sb[];
    __shared__ unsigned sgen;

    const int tid  = threadIdx.x;
    const int cta  = blockIdx.x;
    const int lane = tid & 31;
    const int warp = tid >> 5;       // 0..7
    const int grp  = lane >> 2;      // 0..7
    const int tig  = lane & 3;       // 0..3
    const int wsub = warp & 3;       // m-subtile 0..3
    const int ntb  = (warp >> 2) * 4;  // n-tile base: warps 0-3 -> 0..3, 4-7 -> 4..7

    const int mtile = cta >> 4;      // 0..7  : batch rows mtile*64..+64
    const int ctile = cta & 15;      // 0..15 : hidden units ctile*16..+16
    const int hc0   = ctile * 16;

    float* sD    = (float*)(sb + OFF_D);
    float* sBias = (float*)(sb + OFF_MISC);        // [64]
    float* sWih  = sBias + 64;                     // [64]

    if (tid == 0) sgen = g_bar_gen;
    __syncthreads();

    // epilogue mapping: thread -> (row er, 4 units starting ej)
    const int er = tid & 63;
    const int ej = (tid >> 6) * 4;
    const int gbrow = mtile * 64 + er;

    // fragment base row for this warp's m-subtile
    const int ar0 = wsub * 16 + grp;

    // ================= Layer 0 =================
    {
        for (int idx = tid; idx < 2048; idx += TPB) {
            int rr = idx >> 5, k0 = (idx & 31) * 8;
            int n = (rr >> 4) * Hsz + hc0 + (rr & 15);
            const float* s = w_hh0 + (size_t)n * Hsz + k0;
            float4 f0 = *(const float4*)s, f1 = *(const float4*)(s + 4);
            float fv[8] = {f0.x, f0.y, f0.z, f0.w, f1.x, f1.y, f1.z, f1.w};
            BV8 uh, ul;
            #pragma unroll
            for (int i = 0; i < 8; i++) {
                uh.b[i] = __float2bfloat16(fv[i]);
                ul.b[i] = __float2bfloat16(fv[i] - __bfloat162float(uh.b[i]));
            }
            *(uint4*)(sb + OFF_WHI + (size_t)rr * WSTR + k0 * 2) = uh.v;
            *(uint4*)(sb + OFF_WLO + (size_t)rr * WSTR + k0 * 2) = ul.v;
        }
        for (int idx = tid; idx < 64; idx += TPB) {
            int n = (idx >> 4) * Hsz + hc0 + (idx & 15);
            sBias[idx] = b_ih0[n] + b_hh0[n];
            sWih[idx]  = w_ih0[n];
        }
        __syncthreads();

        float cst[4];
        #pragma unroll
        for (int i = 0; i < 4; i++) cst[i] = 0.f;

        for (int t = 0; t < Tsz; t++) {
            if (t > 0) {
                stage_panel(sb,
                    g_h1_hi + ((size_t)(t - 1) * Bsz + mtile * 64) * Hsz,
                    g_h1_lo + ((size_t)(t - 1) * Bsz + mtile * 64) * Hsz);
                __syncthreads();

                float acc[4][4];
                #pragma unroll
                for (int nt = 0; nt < 4; nt++)
                    #pragma unroll
                    for (int i = 0; i < 4; i++) acc[nt][i] = 0.f;

                #pragma unroll 4
                for (int ks = 0; ks < 16; ks++) {
                    int kb = ks * 16 + 2 * tig;
                    uint32_t ah[4], al[4];
                    ah[0] = *(const uint32_t*)(sb + OFF_AHI + (size_t)ar0 * ASTR + kb * 2);
                    ah[1] = *(const uint32_t*)(sb + OFF_AHI + (size_t)(ar0 + 8) * ASTR + kb * 2);
                    ah[2] = *(const uint32_t*)(sb + OFF_AHI + (size_t)ar0 * ASTR + (kb + 8) * 2);
                    ah[3] = *(const uint32_t*)(sb + OFF_AHI + (size_t)(ar0 + 8) * ASTR + (kb + 8) * 2);
                    al[0] = *(const uint32_t*)(sb + OFF_ALO + (size_t)ar0 * ASTR + kb * 2);
                    al[1] = *(const uint32_t*)(sb + OFF_ALO + (size_t)(ar0 + 8) * ASTR + kb * 2);
                    al[2] = *(const uint32_t*)(sb + OFF_ALO + (size_t)ar0 * ASTR + (kb + 8) * 2);
                    al[3] = *(const uint32_t*)(sb + OFF_ALO + (size_t)(ar0 + 8) * ASTR + (kb + 8) * 2);
                    #pragma unroll
                    for (int nt = 0; nt < 4; nt++) {
                        int bn = (ntb + nt) * 8 + grp;
                        uint32_t bh0 = *(const uint32_t*)(sb + OFF_WHI + (size_t)bn * WSTR + kb * 2);
                        uint32_t bh1 = *(const uint32_t*)(sb + OFF_WHI + (size_t)bn * WSTR + (kb + 8) * 2);
                        uint32_t bl0 = *(const uint32_t*)(sb + OFF_WLO + (size_t)bn * WSTR + kb * 2);
                        uint32_t bl1 = *(const uint32_t*)(sb + OFF_WLO + (size_t)bn * WSTR + (kb + 8) * 2);
                        MMA4(acc[nt], ah, bh0, bh1);
                        MMA4(acc[nt], al, bh0, bh1);
                        MMA4(acc[nt], ah, bl0, bl1);
                    }
                }
                #pragma unroll
                for (int nt = 0; nt < 4; nt++) {
                    int c0 = (ntb + nt) * 8 + 2 * tig;
                    sD[(size_t)ar0 * DSTR + c0]           = acc[nt][0];
                    sD[(size_t)ar0 * DSTR + c0 + 1]       = acc[nt][1];
                    sD[(size_t)(ar0 + 8) * DSTR + c0]     = acc[nt][2];
                    sD[(size_t)(ar0 + 8) * DSTR + c0 + 1] = acc[nt][3];
                }
            }
            __syncthreads();

            // epilogue (4 units/thread)
            float xv = __ldg(x + (size_t)gbrow * Tsz + t);
            BV4 hh, hl;
            #pragma unroll
            for (int q = 0; q < 4; q++) {
                int j = ej + q;
                float pi = sBias[j]      + xv * sWih[j];
                float pf = sBias[16 + j] + xv * sWih[16 + j];
                float pg = sBias[32 + j] + xv * sWih[32 + j];
                float po = sBias[48 + j] + xv * sWih[48 + j];
                if (t > 0) {
                    pi += sD[(size_t)er * DSTR + j];
                    pf += sD[(size_t)er * DSTR + 16 + j];
                    pg += sD[(size_t)er * DSTR + 32 + j];
                    po += sD[(size_t)er * DSTR + 48 + j];
                }
                float iv = sigf(pi), fv = sigf(pf), gv = tanh_f(pg), ov = sigf(po);
                float c  = fmaf(fv, cst[q], iv * gv);
                cst[q] = c;
                float h  = ov * tanh_f(c);
                hh.b[q] = __float2bfloat16(h);
                hl.b[q] = __float2bfloat16(h - __bfloat162float(hh.b[q]));
            }
            size_t ho = ((size_t)t * Bsz + gbrow) * Hsz + hc0 + ej;
            *(uint2*)(g_h1_hi + ho) = hh.v;
            *(uint2*)(g_h1_lo + ho) = hl.v;
            grid_barrier(&sgen);
        }
    }

    // ================= Layer 1 =================
    {
        for (int idx = tid; idx < 4096; idx += TPB) {
            int rr = idx >> 6, k0 = (idx & 63) * 8;
            int n = (rr >> 4) * Hsz + hc0 + (rr & 15);
            const float* s = (k0 < 256) ? (w_ih1 + (size_t)n * Hsz + k0)
                                        : (w_hh1 + (size_t)n * Hsz + (k0 - 256));
            float4 f0 = *(const float4*)s, f1 = *(const float4*)(s + 4);
            float fv[8] = {f0.x, f0.y, f0.z, f0.w, f1.x, f1.y, f1.z, f1.w};
            BV8 uh, ul;
            #pragma unroll
            for (int i = 0; i < 8; i++) {
                uh.b[i] = __float2bfloat16(fv[i]);
                ul.b[i] = __float2bfloat16(fv[i] - __bfloat162float(uh.b[i]));
            }
            *(uint4*)(sb + OFF_WHI + (size_t)rr * WSTR + k0 * 2) = uh.v;
            *(uint4*)(sb + OFF_WLO + (size_t)rr * WSTR + k0 * 2) = ul.v;
        }
        for (int idx = tid; idx < 64; idx += TPB) {
            int n = (idx >> 4) * Hsz + hc0 + (idx & 15);
            sBias[idx] = b_ih1[n] + b_hh1[n];
        }
        // prestage h1[0] (g_h1 is complete: last L0 barrier passed)
        stage_panel(sb, g_h1_hi + (size_t)mtile * 64 * Hsz,
                        g_h1_lo + (size_t)mtile * 64 * Hsz);
        __syncthreads();

        float cst[4];
        #pragma unroll
        for (int i = 0; i < 4; i++) cst[i] = 0.f;

        for (int t = 0; t < Tsz; t++) {
            float acc[4][4];
            #pragma unroll
            for (int nt = 0; nt < 4; nt++)
                #pragma unroll
                for (int i = 0; i < 4; i++) acc[nt][i] = 0.f;

            // ---- panel 0: A = h1[t] (prestaged), W cols [0,256) ----
            #pragma unroll 4
            for (int ks = 0; ks < 16; ks++) {
                int ka = ks * 16 + 2 * tig;
                uint32_t ah[4], al[4];
                ah[0] = *(const uint32_t*)(sb + OFF_AHI + (size_t)ar0 * ASTR + ka * 2);
                ah[1] = *(const uint32_t*)(sb + OFF_AHI + (size_t)(ar0 + 8) * ASTR + ka * 2);
                ah[2] = *(const uint32_t*)(sb + OFF_AHI + (size_t)ar0 * ASTR + (ka + 8) * 2);
                ah[3] = *(const uint32_t*)(sb + OFF_AHI + (size_t)(ar0 + 8) * ASTR + (ka + 8) * 2);
                al[0] = *(const uint32_t*)(sb + OFF_ALO + (size_t)ar0 * ASTR + ka * 2);
                al[1] = *(const uint32_t*)(sb + OFF_ALO + (size_t)(ar0 + 8) * ASTR + ka * 2);
                al[2] = *(const uint32_t*)(sb + OFF_ALO + (size_t)ar0 * ASTR + (ka + 8) * 2);
                al[3] = *(const uint32_t*)(sb + OFF_ALO + (size_t)(ar0 + 8) * ASTR + (ka + 8) * 2);
                #pragma unroll
                for (int nt = 0; nt < 4; nt++) {
                    int bn = (ntb + nt) * 8 + grp;
                    uint32_t bh0 = *(const uint32_t*)(sb + OFF_WHI + (size_t)bn * WSTR + ka * 2);
                    uint32_t bh1 = *(const uint32_t*)(sb + OFF_WHI + (size_t)bn * WSTR + (ka + 8) * 2);
                    uint32_t bl0 = *(const uint32_t*)(sb + OFF_WLO + (size_t)bn * WSTR + ka * 2);
                    uint32_t bl1 = *(const uint32_t*)(sb + OFF_WLO + (size_t)bn * WSTR + (ka + 8) * 2);
                    MMA4(acc[nt], ah, bh0, bh1);
                    MMA4(acc[nt], al, bh0, bh1);
                    MMA4(acc[nt], ah, bl0, bl1);
                }
            }
            __syncthreads();   // done reading h1 panel

            // ---- panel 1: A = h2[t-1], W cols [256,512) ----
            if (t > 0) {
                stage_panel(sb, g_h2_hi[t & 1] + (size_t)mtile * 64 * Hsz,
                                g_h2_lo[t & 1] + (size_t)mtile * 64 * Hsz);
                __syncthreads();
                #pragma unroll 4
                for (int ks = 0; ks < 16; ks++) {
                    int ka = ks * 16 + 2 * tig;
                    int kb = 256 + ka;
                    uint32_t ah[4], al[4];
                    ah[0] = *(const uint32_t*)(sb + OFF_AHI + (size_t)ar0 * ASTR + ka * 2);
                    ah[1] = *(const uint32_t*)(sb + OFF_AHI + (size_t)(ar0 + 8) * ASTR + ka * 2);
                    ah[2] = *(const uint32_t*)(sb + OFF_AHI + (size_t)ar0 * ASTR + (ka + 8) * 2);
                    ah[3] = *(const uint32_t*)(sb + OFF_AHI + (size_t)(ar0 + 8) * ASTR + (ka + 8) * 2);
                    al[0] = *(const uint32_t*)(sb + OFF_ALO + (size_t)ar0 * ASTR + ka * 2);
                    al[1] = *(const uint32_t*)(sb + OFF_ALO + (size_t)(ar0 + 8) * ASTR + ka * 2);
                    al[2] = *(const uint32_t*)(sb + OFF_ALO + (size_t)ar0 * ASTR + (ka + 8) * 2);
                    al[3] = *(const uint32_t*)(sb + OFF_ALO + (size_t)(ar0 + 8) * ASTR + (ka + 8) * 2);
                    #pragma unroll
                    for (int nt = 0; nt < 4; nt++) {
                        int bn = (ntb + nt) * 8 + grp;
                        uint32_t bh0 = *(const uint32_t*)(sb + OFF_WHI + (size_t)bn * WSTR + kb * 2);
                        uint32_t bh1 = *(const uint32_t*)(sb + OFF_WHI + (size_t)bn * WSTR + (kb + 8) * 2);
                        uint32_t bl0 = *(const uint32_t*)(sb + OFF_WLO + (size_t)bn * WSTR + kb * 2);
                        uint32_t bl1 = *(const uint32_t*)(sb + OFF_WLO + (size_t)bn * WSTR + (kb + 8) * 2);
                        MMA4(acc[nt], ah, bh0, bh1);
                        MMA4(acc[nt], al, bh0, bh1);
                        MMA4(acc[nt], ah, bl0, bl1);
                    }
                }
                __syncthreads();   // done reading h2 panel before prestage overwrites
            }

            // write accumulators to D
            #pragma unroll
            for (int nt = 0; nt < 4; nt++) {
                int c0 = (ntb + nt) * 8 + 2 * tig;
                sD[(size_t)ar0 * DSTR + c0]           = acc[nt][0];
                sD[(size_t)ar0 * DSTR + c0 + 1]       = acc[nt][1];
                sD[(size_t)(ar0 + 8) * DSTR + c0]     = acc[nt][2];
                sD[(size_t)(ar0 + 8) * DSTR + c0 + 1] = acc[nt][3];
            }
            __syncthreads();

            // epilogue
            BV4 hh, hl;
            #pragma unroll
            for (int q = 0; q < 4; q++) {
                int j = ej + q;
                float pi = sD[(size_t)er * DSTR + j]      + sBias[j];
                float pf = sD[(size_t)er * DSTR + 16 + j] + sBias[16 + j];
                float pg = sD[(size_t)er * DSTR + 32 + j] + sBias[32 + j];
                float po = sD[(size_t)er * DSTR + 48 + j] + sBias[48 + j];
                float iv = sigf(pi), fv = sigf(pf), gv = tanh_f(pg), ov = sigf(po);
                float c  = fmaf(fv, cst[q], iv * gv);
                cst[q] = c;
                float h  = ov * tanh_f(c);
                hh.b[q] = __float2bfloat16(h);
                hl.b[q] = __float2bfloat16(h - __bfloat162float(hh.b[q]));
            }
            size_t ho = (size_t)gbrow * Hsz + hc0 + ej;
            *(uint2*)(g_h2_hi[(t + 1) & 1] + ho) = hh.v;
            *(uint2*)(g_h2_lo[(t + 1) & 1] + ho) = hl.v;

            // prestage h1[t+1] BEFORE the barrier (no dependency on it)
            if (t + 1 < Tsz) {
                stage_panel(sb,
                    g_h1_hi + ((size_t)(t + 1) * Bsz + mtile * 64) * Hsz,
                    g_h1_lo + ((size_t)(t + 1) * Bsz + mtile * 64) * Hsz);
            }
            grid_barrier(&sgen);
        }
    }

    // ================= Final linear =================
    if (cta < 16) {
        const __nv_bfloat16* hh = g_h2_hi[Tsz & 1];   // == [0]
        const __nv_bfloat16* hl = g_h2_lo[Tsz & 1];
        for (int idx = tid; idx < 32 * Psz; idx += TPB) {
            int b = cta * 32 + idx / Psz;
            int p = idx % Psz;
            const __nv_bfloat16* hr = hh + (size_t)b * Hsz;
            const __nv_bfloat16* lr = hl + (size_t)b * Hsz;
            const float* wr = w_lin + (size_t)p * Hsz;
            float s = b_lin[p];
            for (int k = 0; k < Hsz; k++) {
                float hv = __bfloat162float(hr[k]) + __bfloat162float(lr[k]);
                s = fmaf(hv, wr[k], s);
            }
            out[(size_t)b * Psz + p] = s;
        }
    }
}

extern "C" void kernel_launch(void* const* d_in, const int* in_sizes, int n_in,
                              void* d_out, int out_size) {
    cudaFuncSetAttribute(lstm_hmma_kernel, cudaFuncAttributeMaxDynamicSharedMemorySize, SMEM_DYN);
    lstm_hmma_kernel<<<NCTA, TPB, SMEM_DYN>>>(
        (const float*)d_in[0], (const float*)d_in[1], (const float*)d_in[2],
        (const float*)d_in[3], (const float*)d_in[4], (const float*)d_in[5],
        (const float*)d_in[6], (const float*)d_in[7], (const float*)d_in[8],
        (const float*)d_in[9], (const float*)d_in[10], (float*)d_out);
}

// round 14
// speedup vs baseline: 1.8214x; 1.0082x over previous
#include <cuda_runtime.h>
#include <cuda_bf16.h>
#include <cstdint>
#include <cstddef>

#define NCTA 128
#define TPB  256
constexpr int Bsz = 512;
constexpr int Tsz = 256;
constexpr int Hsz = 256;
constexpr int Psz = 14;

// ---------------- device scratch ----------------
__device__ __nv_bfloat16 g_h1_hi[(size_t)Tsz * Bsz * Hsz];   // 64 MB
__device__ __nv_bfloat16 g_h1_lo[(size_t)Tsz * Bsz * Hsz];   // 64 MB
__device__ __nv_bfloat16 g_h2_hi[2][Bsz * Hsz];
__device__ __nv_bfloat16 g_h2_lo[2][Bsz * Hsz];
__device__ unsigned g_cnt[8 * 32];          // 8 group counters, 128B apart
__device__ unsigned g_root = 0;
__device__ volatile unsigned g_bar_gen = 0;

__device__ __forceinline__ float sigf(float x) { return 1.0f / (1.0f + __expf(-x)); }
__device__ __forceinline__ float tanh_f(float x) {
    x = fmaxf(fminf(x, 15.f), -15.f);
    float e = __expf(-2.f * x);
    return __fdividef(1.f - e, 1.f + e);
}

// Grid barrier v3: two-level arrival tree (8x16 -> 8), busy spin, 1 fence per CTA.
__device__ __forceinline__ void grid_barrier(unsigned* sgen, int cta) {
    __syncthreads();
    if (threadIdx.x == 0) {
        __threadfence();                         // release (cumulative)
        unsigned target = *sgen + 1;
        if (atomicAdd(&g_cnt[(cta & 7) * 32], 1u) == 15u) {
            if (atomicAdd(&g_root, 1u) == 7u) {
                g_root = 0;
                #pragma unroll
                for (int i = 0; i < 8; i++) g_cnt[i * 32] = 0;
                __threadfence();
                g_bar_gen = target;
            } else {
                while (g_bar_gen < target) { }
            }
        } else {
            while (g_bar_gen < target) { }
        }
        __threadfence();                         // acquire
        *sgen = target;
    }
    __syncthreads();
}

// ---------------- smem layout (bytes) ----------------
#define ASTR 528
#define WSTR 1040
#define OFF_AHI 0u
#define OFF_ALO 33792u
#define OFF_WHI 67584u
#define OFF_WLO 134144u
#define OFF_SH  200704u                          // sH: 64 x 17 u32 = 4352 B
#define OFF_MISC 205056u                         // sBias[64], sWih[64]
#define SMEM_DYN (205056 + 512)

#define MMA4(d, a, b0_, b1_) \
  asm volatile("mma.sync.aligned.m16n8k16.row.col.f32.bf16.bf16.f32 " \
   "{%0,%1,%2,%3}, {%4,%5,%6,%7}, {%8,%9}, {%0,%1,%2,%3};\n" \
   : "+f"((d)[0]), "+f"((d)[1]), "+f"((d)[2]), "+f"((d)[3]) \
   : "r"((a)[0]), "r"((a)[1]), "r"((a)[2]), "r"((a)[3]), "r"(b0_), "r"(b1_))

union BV8 { __nv_bfloat16 b[8]; uint4 v; };

// stage a 64x256 bf16 hi/lo panel from gmem into A buffers
__device__ __forceinline__ void stage_panel(unsigned char* sb,
                                            const __nv_bfloat16* shi,
                                            const __nv_bfloat16* slo) {
    for (int idx = threadIdx.x; idx < 2048; idx += TPB) {
        int r = idx >> 5, c8 = (idx & 31) * 8;
        *(uint4*)(sb + OFF_AHI + (size_t)r * ASTR + c8 * 2) =
            __ldcg((const uint4*)(shi + (size_t)r * Hsz + c8));
        *(uint4*)(sb + OFF_ALO + (size_t)r * ASTR + c8 * 2) =
            __ldcg((const uint4*)(slo + (size_t)r * Hsz + c8));
    }
}

__global__ void __launch_bounds__(TPB, 1)
lstm_hmma_kernel(const float* __restrict__ x,
                 const float* __restrict__ w_ih0, const float* __restrict__ w_hh0,
                 const float* __restrict__ b_ih0, const float* __restrict__ b_hh0,
                 const float* __restrict__ w_ih1, const float* __restrict__ w_hh1,
                 const float* __restrict__ b_ih1, const float* __restrict__ b_hh1,
                 const float* __restrict__ w_lin, const float* __restrict__ b_lin,
                 float* __restrict__ out)
{
    extern __shared__ __align__(16) unsigned char sb[];
    __shared__ unsigned sgen;

    const int tid  = threadIdx.x;
    const int cta  = blockIdx.x;
    const int lane = tid & 31;
    const int warp = tid >> 5;         // 0..7
    const int grp  = lane >> 2;        // 0..7
    const int tig  = lane & 3;         // 0..3
    const int wsub = warp & 3;         // m-subtile 0..3
    const int ntb  = (warp >> 2) * 4;  // n-tile base: 0 or 4

    const int mtile = cta >> 4;        // 0..7  : batch rows mtile*64..+64
    const int ctile = cta & 15;        // 0..15 : hidden units ctile*16..+16
    const int hc0   = ctile * 16;

    unsigned* sH = (unsigned*)(sb + OFF_SH);       // [64][17]
    float* sBias = (float*)(sb + OFF_MISC);        // [64] unit-major: [u*4+g]
    float* sWih  = sBias + 64;                     // [64]

    if (tid == 0) sgen = g_bar_gen;
    __syncthreads();

    // fragment base row for this warp's m-subtile
    const int ar0  = wsub * 16 + grp;
    // epilogue: this thread's row and row-parity after the gate shuffle
    const int rloc = ar0 + ((tig & 1) << 3);       // local row 0..63

    // ================= Layer 0 =================
    {
        // stage W_hh0, UNIT-MAJOR cols: col rr = unit*4 + gate -> n = gate*256 + hc0 + unit
        for (int idx = tid; idx < 2048; idx += TPB) {
            int rr = idx >> 5, k0 = (idx & 31) * 8;
            int n = (rr & 3) * Hsz + hc0 + (rr >> 2);
            const float* s = w_hh0 + (size_t)n * Hsz + k0;
            float4 f0 = *(const float4*)s, f1 = *(const float4*)(s + 4);
            float fv[8] = {f0.x, f0.y, f0.z, f0.w, f1.x, f1.y, f1.z, f1.w};
            BV8 uh, ul;
            #pragma unroll
            for (int i = 0; i < 8; i++) {
                uh.b[i] = __float2bfloat16(fv[i]);
                ul.b[i] = __float2bfloat16(fv[i] - __bfloat162float(uh.b[i]));
            }
            *(uint4*)(sb + OFF_WHI + (size_t)rr * WSTR + k0 * 2) = uh.v;
            *(uint4*)(sb + OFF_WLO + (size_t)rr * WSTR + k0 * 2) = ul.v;
        }
        for (int idx = tid; idx < 64; idx += TPB) {
            int n = (idx & 3) * Hsz + hc0 + (idx >> 2);   // [u*4+g]
            sBias[idx] = b_ih0[n] + b_hh0[n];
            sWih[idx]  = w_ih0[n];
        }
        __syncthreads();

        float cst[4];
        #pragma unroll
        for (int i = 0; i < 4; i++) cst[i] = 0.f;

        for (int t = 0; t < Tsz; t++) {
            float acc[4][4];
            #pragma unroll
            for (int nt = 0; nt < 4; nt++)
                #pragma unroll
                for (int i = 0; i < 4; i++) acc[nt][i] = 0.f;

            if (t > 0) {
                stage_panel(sb,
                    g_h1_hi + ((size_t)(t - 1) * Bsz + mtile * 64) * Hsz,
                    g_h1_lo + ((size_t)(t - 1) * Bsz + mtile * 64) * Hsz);
                __syncthreads();

                #pragma unroll 4
                for (int ks = 0; ks < 16; ks++) {
                    int kb = ks * 16 + 2 * tig;
                    uint32_t ah[4], al[4];
                    ah[0] = *(const uint32_t*)(sb + OFF_AHI + (size_t)ar0 * ASTR + kb * 2);
                    ah[1] = *(const uint32_t*)(sb + OFF_AHI + (size_t)(ar0 + 8) * ASTR + kb * 2);
                    ah[2] = *(const uint32_t*)(sb + OFF_AHI + (size_t)ar0 * ASTR + (kb + 8) * 2);
                    ah[3] = *(const uint32_t*)(sb + OFF_AHI + (size_t)(ar0 + 8) * ASTR + (kb + 8) * 2);
                    al[0] = *(const uint32_t*)(sb + OFF_ALO + (size_t)ar0 * ASTR + kb * 2);
                    al[1] = *(const uint32_t*)(sb + OFF_ALO + (size_t)(ar0 + 8) * ASTR + kb * 2);
                    al[2] = *(const uint32_t*)(sb + OFF_ALO + (size_t)ar0 * ASTR + (kb + 8) * 2);
                    al[3] = *(const uint32_t*)(sb + OFF_ALO + (size_t)(ar0 + 8) * ASTR + (kb + 8) * 2);
                    #pragma unroll
                    for (int nt = 0; nt < 4; nt++) {
                        int bn = (ntb + nt) * 8 + grp;
                        uint32_t bh0 = *(const uint32_t*)(sb + OFF_WHI + (size_t)bn * WSTR + kb * 2);
                        uint32_t bh1 = *(const uint32_t*)(sb + OFF_WHI + (size_t)bn * WSTR + (kb + 8) * 2);
                        uint32_t bl0 = *(const uint32_t*)(sb + OFF_WLO + (size_t)bn * WSTR + kb * 2);
                        uint32_t bl1 = *(const uint32_t*)(sb + OFF_WLO + (size_t)bn * WSTR + (kb + 8) * 2);
                        MMA4(acc[nt], ah, bh0, bh1);
                        MMA4(acc[nt], al, bh0, bh1);
                        MMA4(acc[nt], ah, bl0, bl1);
                    }
                }
            }

            // register epilogue: shuffle gates, compute LSTM cell, write sH
            float xv = __ldg(x + (size_t)(mtile * 64 + rloc) * Tsz + t);
            #pragma unroll
            for (int nt = 0; nt < 4; nt++) {
                float s0 = (tig & 1) ? acc[nt][0] : acc[nt][2];
                float s1 = (tig & 1) ? acc[nt][1] : acc[nt][3];
                float r0 = __shfl_xor_sync(0xffffffffu, s0, 1);
                float r1 = __shfl_xor_sync(0xffffffffu, s1, 1);
                float gi, gf, gg, go;
                if (tig & 1) { gi = r0;         gf = r1;         gg = acc[nt][2]; go = acc[nt][3]; }
                else         { gi = acc[nt][0]; gf = acc[nt][1]; gg = r0;         go = r1;         }
                int u  = 2 * (ntb + nt) + (tig >> 1);
                int jb = u * 4;
                float pi = sBias[jb + 0] + xv * sWih[jb + 0] + gi;
                float pf = sBias[jb + 1] + xv * sWih[jb + 1] + gf;
                float pg = sBias[jb + 2] + xv * sWih[jb + 2] + gg;
                float po = sBias[jb + 3] + xv * sWih[jb + 3] + go;
                float iv = sigf(pi), fv = sigf(pf), gv = tanh_f(pg), ov = sigf(po);
                float c  = fmaf(fv, cst[nt], iv * gv);
                cst[nt] = c;
                float h  = ov * tanh_f(c);
                __nv_bfloat16 bh = __float2bfloat16(h);
                __nv_bfloat16 bl = __float2bfloat16(h - __bfloat162float(bh));
                sH[rloc * 17 + u] = (unsigned)__bfloat16_as_ushort(bh)
                                  | ((unsigned)__bfloat16_as_ushort(bl) << 16);
            }
            __syncthreads();

            // coalesced store pass: 256 threads = 64 rows x 4 chunks of 4 units
            {
                int row = tid >> 2, c4 = (tid & 3) * 4;
                unsigned w0 = sH[row * 17 + c4],     w1 = sH[row * 17 + c4 + 1];
                unsigned w2 = sH[row * 17 + c4 + 2], w3 = sH[row * 17 + c4 + 3];
                uint2 hv, lv;
                hv.x = (w0 & 0xFFFFu) | (w1 << 16);
                hv.y = (w2 & 0xFFFFu) | (w3 << 16);
                lv.x = (w0 >> 16) | (w1 & 0xFFFF0000u);
                lv.y = (w2 >> 16) | (w3 & 0xFFFF0000u);
                size_t off = ((size_t)t * Bsz + mtile * 64 + row) * Hsz + hc0 + c4;
                *(uint2*)(g_h1_hi + off) = hv;
                *(uint2*)(g_h1_lo + off) = lv;
            }
            grid_barrier(&sgen, cta);
        }
    }

    // ================= Layer 1 =================
    {
        // stage [w_ih1 | w_hh1], unit-major cols
        for (int idx = tid; idx < 4096; idx += TPB) {
            int rr = idx >> 6, k0 = (idx & 63) * 8;
            int n = (rr & 3) * Hsz + hc0 + (rr >> 2);
            const float* s = (k0 < 256) ? (w_ih1 + (size_t)n * Hsz + k0)
                                        : (w_hh1 + (size_t)n * Hsz + (k0 - 256));
            float4 f0 = *(const float4*)s, f1 = *(const float4*)(s + 4);
            float fv[8] = {f0.x, f0.y, f0.z, f0.w, f1.x, f1.y, f1.z, f1.w};
            BV8 uh, ul;
            #pragma unroll
            for (int i = 0; i < 8; i++) {
                uh.b[i] = __float2bfloat16(fv[i]);
                ul.b[i] = __float2bfloat16(fv[i] - __bfloat162float(uh.b[i]));
            }
            *(uint4*)(sb + OFF_WHI + (size_t)rr * WSTR + k0 * 2) = uh.v;
            *(uint4*)(sb + OFF_WLO + (size_t)rr * WSTR + k0 * 2) = ul.v;
        }
        for (int idx = tid; idx < 64; idx += TPB) {
            int n = (idx & 3) * Hsz + hc0 + (idx >> 2);
            sBias[idx] = b_ih1[n] + b_hh1[n];
        }
        // prestage h1[0]
        stage_panel(sb, g_h1_hi + (size_t)mtile * 64 * Hsz,
                        g_h1_lo + (size_t)mtile * 64 * Hsz);
        __syncthreads();

        float cst[4];
        #pragma unroll
        for (int i = 0; i < 4; i++) cst[i] = 0.f;

        for (int t = 0; t < Tsz; t++) {
            float acc[4][4];
            #pragma unroll
            for (int nt = 0; nt < 4; nt++)
                #pragma unroll
                for (int i = 0; i < 4; i++) acc[nt][i] = 0.f;

            // ---- panel 0: A = h1[t] (prestaged), W cols [0,256) ----
            #pragma unroll 4
            for (int ks = 0; ks < 16; ks++) {
                int ka = ks * 16 + 2 * tig;
                uint32_t ah[4], al[4];
                ah[0] = *(const uint32_t*)(sb + OFF_AHI + (size_t)ar0 * ASTR + ka * 2);
                ah[1] = *(const uint32_t*)(sb + OFF_AHI + (size_t)(ar0 + 8) * ASTR + ka * 2);
                ah[2] = *(const uint32_t*)(sb + OFF_AHI + (size_t)ar0 * ASTR + (ka + 8) * 2);
                ah[3] = *(const uint32_t*)(sb + OFF_AHI + (size_t)(ar0 + 8) * ASTR + (ka + 8) * 2);
                al[0] = *(const uint32_t*)(sb + OFF_ALO + (size_t)ar0 * ASTR + ka * 2);
                al[1] = *(const uint32_t*)(sb + OFF_ALO + (size_t)(ar0 + 8) * ASTR + ka * 2);
                al[2] = *(const uint32_t*)(sb + OFF_ALO + (size_t)ar0 * ASTR + (ka + 8) * 2);
                al[3] = *(const uint32_t*)(sb + OFF_ALO + (size_t)(ar0 + 8) * ASTR + (ka + 8) * 2);
                #pragma unroll
                for (int nt = 0; nt < 4; nt++) {
                    int bn = (ntb + nt) * 8 + grp;
                    uint32_t bh0 = *(const uint32_t*)(sb + OFF_WHI + (size_t)bn * WSTR + ka * 2);
                    uint32_t bh1 = *(const uint32_t*)(sb + OFF_WHI + (size_t)bn * WSTR + (ka + 8) * 2);
                    uint32_t bl0 = *(const uint32_t*)(sb + OFF_WLO + (size_t)bn * WSTR + ka * 2);
                    uint32_t bl1 = *(const uint32_t*)(sb + OFF_WLO + (size_t)bn * WSTR + (ka + 8) * 2);
                    MMA4(acc[nt], ah, bh0, bh1);
                    MMA4(acc[nt], al, bh0, bh1);
                    MMA4(acc[nt], ah, bl0, bl1);
                }
            }
            __syncthreads();   // done reading h1 panel

            // ---- panel 1: A = h2[t-1], W cols [256,512) ----
            if (t > 0) {
                stage_panel(sb, g_h2_hi[t & 1] + (size_t)mtile * 64 * Hsz,
                                g_h2_lo[t & 1] + (size_t)mtile * 64 * Hsz);
                __syncthreads();
                #pragma unroll 4
                for (int ks = 0; ks < 16; ks++) {
                    int ka = ks * 16 + 2 * tig;
                    int kb = 256 + ka;
                    uint32_t ah[4], al[4];
                    ah[0] = *(const uint32_t*)(sb + OFF_AHI + (size_t)ar0 * ASTR + ka * 2);
                    ah[1] = *(const uint32_t*)(sb + OFF_AHI + (size_t)(ar0 + 8) * ASTR + ka * 2);
                    ah[2] = *(const uint32_t*)(sb + OFF_AHI + (size_t)ar0 * ASTR + (ka + 8) * 2);
                    ah[3] = *(const uint32_t*)(sb + OFF_AHI + (size_t)(ar0 + 8) * ASTR + (ka + 8) * 2);
                    al[0] = *(const uint32_t*)(sb + OFF_ALO + (size_t)ar0 * ASTR + ka * 2);
                    al[1] = *(const uint32_t*)(sb + OFF_ALO + (size_t)(ar0 + 8) * ASTR + ka * 2);
                    al[2] = *(const uint32_t*)(sb + OFF_ALO + (size_t)ar0 * ASTR + (ka + 8) * 2);
                    al[3] = *(const uint32_t*)(sb + OFF_ALO + (size_t)(ar0 + 8) * ASTR + (ka + 8) * 2);
                    #pragma unroll
                    for (int nt = 0; nt < 4; nt++) {
                        int bn = (ntb + nt) * 8 + grp;
                        uint32_t bh0 = *(const uint32_t*)(sb + OFF_WHI + (size_t)bn * WSTR + kb * 2);
                        uint32_t bh1 = *(const uint32_t*)(sb + OFF_WHI + (size_t)bn * WSTR + (kb + 8) * 2);
                        uint32_t bl0 = *(const uint32_t*)(sb + OFF_WLO + (size_t)bn * WSTR + kb * 2);
                        uint32_t bl1 = *(const uint32_t*)(sb + OFF_WLO + (size_t)bn * WSTR + (kb + 8) * 2);
                        MMA4(acc[nt], ah, bh0, bh1);
                        MMA4(acc[nt], al, bh0, bh1);
                        MMA4(acc[nt], ah, bl0, bl1);
                    }
                }
            }

            // register epilogue
            #pragma unroll
            for (int nt = 0; nt < 4; nt++) {
                float s0 = (tig & 1) ? acc[nt][0] : acc[nt][2];
                float s1 = (tig & 1) ? acc[nt][1] : acc[nt][3];
                float r0 = __shfl_xor_sync(0xffffffffu, s0, 1);
                float r1 = __shfl_xor_sync(0xffffffffu, s1, 1);
                float gi, gf, gg, go;
                if (tig & 1) { gi = r0;         gf = r1;         gg = acc[nt][2]; go = acc[nt][3]; }
                else         { gi = acc[nt][0]; gf = acc[nt][1]; gg = r0;         go = r1;         }
                int u  = 2 * (ntb + nt) + (tig >> 1);
                int jb = u * 4;
                float pi = gi + sBias[jb + 0];
                float pf = gf + sBias[jb + 1];
                float pg = gg + sBias[jb + 2];
                float po = go + sBias[jb + 3];
                float iv = sigf(pi), fv = sigf(pf), gv = tanh_f(pg), ov = sigf(po);
                float c  = fmaf(fv, cst[nt], iv * gv);
                cst[nt] = c;
                float h  = ov * tanh_f(c);
                __nv_bfloat16 bh = __float2bfloat16(h);
                __nv_bfloat16 bl = __float2bfloat16(h - __bfloat162float(bh));
                sH[rloc * 17 + u] = (unsigned)__bfloat16_as_ushort(bh)
                                  | ((unsigned)__bfloat16_as_ushort(bl) << 16);
            }
            __syncthreads();   // sH ready; also: all warps done reading A(h2)

            // coalesced store pass
            {
                int row = tid >> 2, c4 = (tid & 3) * 4;
                unsigned w0 = sH[row * 17 + c4],     w1 = sH[row * 17 + c4 + 1];
                unsigned w2 = sH[row * 17 + c4 + 2], w3 = sH[row * 17 + c4 + 3];
                uint2 hv, lv;
                hv.x = (w0 & 0xFFFFu) | (w1 << 16);
                hv.y = (w2 & 0xFFFFu) | (w3 << 16);
                lv.x = (w0 >> 16) | (w1 & 0xFFFF0000u);
                lv.y = (w2 >> 16) | (w3 & 0xFFFF0000u);
                size_t off = ((size_t)(mtile * 64 + row)) * Hsz + hc0 + c4;
                *(uint2*)(g_h2_hi[(t + 1) & 1] + off) = hv;
                *(uint2*)(g_h2_lo[(t + 1) & 1] + off) = lv;
            }

            // prestage h1[t+1] BEFORE the barrier (A free: sync above covered readers)
            if (t + 1 < Tsz) {
                stage_panel(sb,
                    g_h1_hi + ((size_t)(t + 1) * Bsz + mtile * 64) * Hsz,
                    g_h1_lo + ((size_t)(t + 1) * Bsz + mtile * 64) * Hsz);
            }
            grid_barrier(&sgen, cta);
        }
    }

    // ================= Final linear =================
    if (cta < 16) {
        const __nv_bfloat16* hh = g_h2_hi[Tsz & 1];   // == [0]
        const __nv_bfloat16* hl = g_h2_lo[Tsz & 1];
        for (int idx = tid; idx < 32 * Psz; idx += TPB) {
            int b = cta * 32 + idx / Psz;
            int p = idx % Psz;
            const __nv_bfloat16* hr = hh + (size_t)b * Hsz;
            const __nv_bfloat16* lr = hl + (size_t)b * Hsz;
            const float* wr = w_lin + (size_t)p * Hsz;
            float s = b_lin[p];
            for (int k = 0; k < Hsz; k++) {
                float hv = __bfloat162float(hr[k]) + __bfloat162float(lr[k]);
                s = fmaf(hv, wr[k], s);
            }
            out[(size_t)b * Psz + p] = s;
        }
    }
}

extern "C" void kernel_launch(void* const* d_in, const int* in_sizes, int n_in,
                              void* d_out, int out_size) {
    cudaFuncSetAttribute(lstm_hmma_kernel, cudaFuncAttributeMaxDynamicSharedMemorySize, SMEM_DYN);
    lstm_hmma_kernel<<<NCTA, TPB, SMEM_DYN>>>(
        (const float*)d_in[0], (const float*)d_in[1], (const float*)d_in[2],
        (const float*)d_in[3], (const float*)d_in[4], (const float*)d_in[5],
        (const float*)d_in[6], (const float*)d_in[7], (const float*)d_in[8],
        (const float*)d_in[9], (const float*)d_in[10], (float*)d_out);
}